// round 11
// baseline (speedup 1.0000x reference)
#include <cuda_runtime.h>
#include <cuda_bf16.h>
#include <cstdint>
#include <cstddef>

// Problem dims: B=32, S=1024, D=256, L=4, O=64, V=5. Two encodes -> 64 seqs.
#define NROWS 65536          // 2 * 32 * 1024

// ---------------- device scratch (static; no runtime allocation) ----------------
__device__ float g_h  [(size_t)NROWS * 256];   // residual stream
__device__ float g_hn [(size_t)NROWS * 256];   // LN out, later reused as gated "c"
__device__ float g_f  [(size_t)NROWS * 256];   // forward GRU out
__device__ float g_r  [(size_t)NROWS * 256];   // reverse GRU out (natural time order)
__device__ float g_xif[(size_t)NROWS * 768];   // xi forward
__device__ float g_xir[(size_t)NROWS * 768];   // xi reverse
__device__ float g_pool[4 * 32 * 256];         // [s-chunk][batch][d] partial sums
__device__ float g_hbuf[8 * 2 * 16 * 256];     // [group][parity][row16][unit256]
__device__ unsigned g_cnt[8 * 64];             // one counter per 256B (avoid line contention)

// ---------------- helpers ----------------
__device__ __forceinline__ unsigned f2tfu(float x) {
    unsigned u; asm("cvt.rna.tf32.f32 %0, %1;" : "=r"(u) : "f"(x)); return u;
}
__device__ __forceinline__ float f2tff(float x) {
    return __uint_as_float(f2tfu(x));
}
__device__ __forceinline__ void mma_tf32(float* c, const unsigned* a, unsigned b0, unsigned b1) {
    asm volatile(
        "mma.sync.aligned.m16n8k8.row.col.f32.tf32.tf32.f32 "
        "{%0,%1,%2,%3}, {%4,%5,%6,%7}, {%8,%9}, {%0,%1,%2,%3};\n"
        : "+f"(c[0]), "+f"(c[1]), "+f"(c[2]), "+f"(c[3])
        : "r"(a[0]), "r"(a[1]), "r"(a[2]), "r"(a[3]), "r"(b0), "r"(b1));
}
__device__ __forceinline__ unsigned ld_acq(const unsigned* p) {
    unsigned v; asm volatile("ld.global.acquire.gpu.u32 %0, [%1];" : "=r"(v) : "l"(p)); return v;
}
__device__ __forceinline__ void red_rel(unsigned* p, unsigned v) {
    asm volatile("red.release.gpu.global.add.u32 [%0], %1;" :: "l"(p), "r"(v) : "memory");
}
__device__ __forceinline__ float sigf(float x) { return 1.0f / (1.0f + expf(-x)); }
__device__ __forceinline__ void cp16(void* s, const void* gp) {
    unsigned sa = (unsigned)__cvta_generic_to_shared(s);
    asm volatile("cp.async.cg.shared.global [%0], [%1], 16;\n" :: "r"(sa), "l"(gp));
}
__device__ __forceinline__ void cp_commit() { asm volatile("cp.async.commit_group;\n"); }
template <int N> __device__ __forceinline__ void cp_wait() {
    asm volatile("cp.async.wait_group %0;\n" :: "n"(N));
}

// ---------------- embedding (both encodes) ----------------
__global__ void embed_kernel(const int* __restrict__ tok, const float* __restrict__ emb,
                             const float* __restrict__ pos) {
    int bid = blockIdx.x;
    int d = threadIdx.x;
    int e = bid >> 15, rem = bid & 32767, b = rem >> 10, s = rem & 1023;
    int t;
    if (e == 0) t = tok[b * 1024 + s];
    else { int t0 = tok[b * 1024 + (1023 - s)]; t = (t0 < 4) ? (3 - t0) : 4; }
    g_h[(size_t)bid * 256 + d] = emb[t * 256 + d] + pos[s * 256 + d];
}

// ---------------- layernorm over D=256 (one warp per row, 8 rows per CTA) ----------------
__global__ void ln_kernel(const float* __restrict__ X, const float* __restrict__ gw,
                          const float* __restrict__ gb, float* __restrict__ Y) {
    int warp = threadIdx.x >> 5, lane = threadIdx.x & 31;
    int row = blockIdx.x * 8 + warp;
    const float* x = X + (size_t)row * 256;
    float v[8];
#pragma unroll
    for (int i = 0; i < 8; i++) v[i] = x[lane + i * 32];
    float s = 0.f;
#pragma unroll
    for (int i = 0; i < 8; i++) s += v[i];
#pragma unroll
    for (int o = 16; o > 0; o >>= 1) s += __shfl_xor_sync(0xffffffffu, s, o);
    float m = s * (1.0f / 256.0f);
    float q = 0.f;
#pragma unroll
    for (int i = 0; i < 8; i++) { float d = v[i] - m; q += d * d; }
#pragma unroll
    for (int o = 16; o > 0; o >>= 1) q += __shfl_xor_sync(0xffffffffu, q, o);
    float rs = rsqrtf(q * (1.0f / 256.0f) + 1e-5f);
    float* y = Y + (size_t)row * 256;
#pragma unroll
    for (int i = 0; i < 8; i++) {
        int d = lane + i * 32;
        y[d] = (v[i] - m) * rs * gw[d] + gb[d];
    }
}

// ---------------- tf32 GEMM with cp.async 2-stage pipeline ----------------
// MODE 0: xi   (K=256, N=768, plain + bias)
// MODE 1: gate (K=512: k<256 from A=f, k>=256 from A2=r; N=256; out = g*f+(1-g)*r)
// MODE 2: oproj(K=256, N=256; out += val + bias  (residual))
#define GEMM_SMEM (2 * (128 * 36 + 64 * 36) * 4)

template <int MODE>
__global__ __launch_bounds__(256)
void gemm_kernel(const float* __restrict__ A, const float* __restrict__ A2,
                 const float* __restrict__ W, const float* __restrict__ bias,
                 float* __restrict__ out) {
    extern __shared__ float smg[];
    float* sAb = smg;                  // 2 x 128 x 36
    float* sBb = smg + 2 * 128 * 36;   // 2 x 64 x 36
    const int KT  = (MODE == 1) ? 512 : 256;
    const int WLD = (MODE == 1) ? 512 : 256;
    const int NIT = KT / 32;
    int tid = threadIdx.x, lane = tid & 31, warp = tid >> 5;
    int wm = warp >> 1, wn = warp & 1;
    int rowBase = blockIdx.y * 128;
    int colBase = blockIdx.x * 64;
    int g = lane >> 2, q = lane & 3;

    float acc[2][4][4];
#pragma unroll
    for (int a = 0; a < 2; a++)
#pragma unroll
        for (int b = 0; b < 4; b++)
#pragma unroll
            for (int c = 0; c < 4; c++) acc[a][b][c] = 0.f;

    auto stage = [&](int bsel, int k0) {
        const float* Asrc = (MODE == 1 && k0 >= 256) ? A2 : A;
        int kA = (MODE == 1) ? (k0 & 255) : k0;
        float* dA = sAb + bsel * 128 * 36;
#pragma unroll
        for (int i = 0; i < 4; i++) {
            int flat = tid + i * 256;
            int r = flat >> 3, c4 = flat & 7;
            cp16(&dA[r * 36 + c4 * 4], &Asrc[(size_t)(rowBase + r) * 256 + kA + c4 * 4]);
        }
        float* dB = sBb + bsel * 64 * 36;
#pragma unroll
        for (int i = 0; i < 2; i++) {
            int flat = tid + i * 256;
            int r = flat >> 3, c4 = flat & 7;
            cp16(&dB[r * 36 + c4 * 4], &W[(size_t)(colBase + r) * WLD + k0 + c4 * 4]);
        }
    };

    stage(0, 0); cp_commit();
    for (int it = 0; it < NIT; it++) {
        if (it + 1 < NIT) { stage((it + 1) & 1, (it + 1) * 32); cp_commit(); cp_wait<1>(); }
        else cp_wait<0>();
        __syncthreads();
        const float* sA = sAb + (it & 1) * 128 * 36;
        const float* sB = sBb + (it & 1) * 64 * 36;
#pragma unroll
        for (int kk = 0; kk < 4; kk++) {
            int ko = kk * 8;
            unsigned a[2][4];
#pragma unroll
            for (int mt = 0; mt < 2; mt++) {
                int rb2 = wm * 32 + mt * 16;
                a[mt][0] = __float_as_uint(sA[(rb2 + g) * 36 + ko + q]);
                a[mt][1] = __float_as_uint(sA[(rb2 + g + 8) * 36 + ko + q]);
                a[mt][2] = __float_as_uint(sA[(rb2 + g) * 36 + ko + q + 4]);
                a[mt][3] = __float_as_uint(sA[(rb2 + g + 8) * 36 + ko + q + 4]);
            }
#pragma unroll
            for (int nt = 0; nt < 4; nt++) {
                int nb = wn * 32 + nt * 8;
                unsigned b0 = __float_as_uint(sB[(nb + g) * 36 + ko + q]);
                unsigned b1 = __float_as_uint(sB[(nb + g) * 36 + ko + q + 4]);
                mma_tf32(acc[0][nt], a[0], b0, b1);
                mma_tf32(acc[1][nt], a[1], b0, b1);
            }
        }
        __syncthreads();
    }
    // epilogue
#pragma unroll
    for (int mt = 0; mt < 2; mt++)
#pragma unroll
        for (int nt = 0; nt < 4; nt++)
#pragma unroll
            for (int i = 0; i < 4; i++) {
                int row = rowBase + wm * 32 + mt * 16 + g + ((i & 2) ? 8 : 0);
                int coln = colBase + wn * 32 + nt * 8 + 2 * q + (i & 1);
                float val = acc[mt][nt][i] + bias[coln];
                if (MODE == 0) {
                    out[(size_t)row * 768 + coln] = val;
                } else if (MODE == 1) {
                    float gg = sigf(val);
                    float fv = A [(size_t)row * 256 + coln];
                    float rv = A2[(size_t)row * 256 + coln];
                    out[(size_t)row * 256 + coln] = gg * fv + (1.0f - gg) * rv;
                } else {
                    out[(size_t)row * 256 + coln] += val;
                }
            }
}

// ---------------- persistent bidirectional GRU scan ----------------
// 64 CTAs x 256 threads: dir(2) x batch-slice(4, 16 rows) x unit-slice(8, 32 units).
// Group = dir*4+bs (8 CTAs) exchanges h via double-buffered g_hbuf (L2) with a
// release/acquire counter. 8 warps = 2 n-halves x 4 k-quarters; per-warp work
// identical to the R8 config (96 weight regs, 48 MMAs).
#define RNN_SMEM ((96*260 + 16*260 + 4*16*104 + 96) * 4)

__global__ __launch_bounds__(256)
void rnn_kernel(const float* __restrict__ whhF, const float* __restrict__ whhR,
                const float* __restrict__ bhhF, const float* __restrict__ bhhR) {
    extern __shared__ float sm[];
    float* sW   = sm;                  // 96 x 260 (tf32)  [init only]
    float* sH   = sW + 96 * 260;       // 16 x 260 (tf32 h tile)
    float* sRed = sH + 16 * 260;       // 4 k-quarters x 16 x 104 partials
    float* sBhh = sRed + 4 * 16 * 104; // 96

    int cta = blockIdx.x;              // 0..63
    int dir = cta >> 5, rem = cta & 31, bs = rem >> 3, u8 = rem & 7;
    int group = dir * 4 + bs;
    const float* W    = dir ? whhR : whhF;
    const float* bhh  = dir ? bhhR : bhhF;
    const float* xi   = dir ? g_xir : g_xif;
    float*       outp = dir ? g_r   : g_f;
    float*    buf = g_hbuf + (size_t)group * 8192;   // 2 x 16 x 256
    unsigned* cnt = &g_cnt[group * 64];

    int tid = threadIdx.x, lane = tid & 31, warp = tid >> 5;
    int wn = warp >> 2, wk = warp & 3;    // n-half, k-quarter
    int g = lane >> 2, q = lane & 3;
    int kbase = wk * 64;

    // weight slice: local rows 0..95 = gate(gi=row>>5) x unit(row&31); tf32 in SMEM
    for (int idx = tid; idx < 96 * 256; idx += 256) {
        int rI = idx >> 8, k = idx & 255;
        int gi = rI >> 5, un = rI & 31;
        sW[rI * 260 + k] = f2tff(W[(size_t)(gi * 256 + u8 * 32 + un) * 256 + k]);
    }
    if (tid < 96) {
        int gi = tid >> 5, un = tid & 31;
        sBhh[tid] = bhh[gi * 256 + u8 * 32 + un];
    }
    // zero my 32 unit-columns of parity-0 buffer
    for (int idx = tid; idx < 512; idx += 256) {
        int lr = idx >> 5, c = idx & 31;
        buf[lr * 256 + u8 * 32 + c] = 0.f;
    }
    __syncthreads();

    // hoist Whh fragments: rows wn*48 + j*8 + g, k-quarter kbase
    unsigned bfr[8][6][2];
#pragma unroll
    for (int ks = 0; ks < 8; ks++) {
        int k0 = kbase + ks * 8;
#pragma unroll
        for (int j = 0; j < 6; j++) {
            int row = wn * 48 + j * 8 + g;
            bfr[ks][j][0] = __float_as_uint(sW[row * 260 + k0 + q]);
            bfr[ks][j][1] = __float_as_uint(sW[row * 260 + k0 + q + 4]);
        }
    }

    if (tid == 0) red_rel(cnt, 1u);
    unsigned target = 8u;
    while (ld_acq(cnt) < target) {}

    // per-thread cell mapping: unit uc (0..31), rows lr0/lr1
    int uc = tid & 31;
    int gu = u8 * 32 + uc;
    int lr0 = tid >> 5;        // 0..7
    int lr1 = lr0 + 8;         // 8..15

    float hpc0 = 0.f, hpc1 = 0.f;   // h_0 = 0 carried in regs

    // xi prefetch for t=0
    float xr0, xz0, xn0, xr1, xz1, xn1;
    {
        int tt = dir ? 1023 : 0;
        const float* x0 = xi + ((size_t)(bs * 16 + lr0) * 1024 + tt) * 768;
        const float* x1 = xi + ((size_t)(bs * 16 + lr1) * 1024 + tt) * 768;
        xr0 = x0[gu]; xz0 = x0[256 + gu]; xn0 = x0[512 + gu];
        xr1 = x1[gu]; xz1 = x1[256 + gu]; xn1 = x1[512 + gu];
    }

    for (int t = 0; t < 1024; t++) {
        int par = t & 1;
        int ttime = dir ? (1023 - t) : t;
        size_t row0 = (size_t)(bs * 16 + lr0) * 1024 + ttime;
        size_t row1 = (size_t)(bs * 16 + lr1) * 1024 + ttime;

        // stage full h tile (16 x 256 = 1024 float4), 4 float4/thread, tf32
#pragma unroll
        for (int it = 0; it < 4; it++) {
            int idx = tid + it * 256;          // 0..1023
            int lr = idx >> 6, c4 = idx & 63;
            float4 v = *(const float4*)&buf[par * 4096 + lr * 256 + c4 * 4];
            float4 w;
            w.x = f2tff(v.x); w.y = f2tff(v.y); w.z = f2tff(v.z); w.w = f2tff(v.w);
            *(float4*)&sH[lr * 260 + c4 * 4] = w;
        }
        __syncthreads();

        // MMA: 16 x 48(n-half) over this warp's k-quarter; b register-resident
        float c[6][4];
#pragma unroll
        for (int j = 0; j < 6; j++)
#pragma unroll
            for (int i = 0; i < 4; i++) c[j][i] = 0.f;
#pragma unroll
        for (int ks = 0; ks < 8; ks++) {
            int k0 = kbase + ks * 8;
            unsigned a[4];
            a[0] = __float_as_uint(sH[g * 260 + k0 + q]);
            a[1] = __float_as_uint(sH[(g + 8) * 260 + k0 + q]);
            a[2] = __float_as_uint(sH[g * 260 + k0 + q + 4]);
            a[3] = __float_as_uint(sH[(g + 8) * 260 + k0 + q + 4]);
#pragma unroll
            for (int j = 0; j < 6; j++)
                mma_tf32(c[j], a, bfr[ks][j][0], bfr[ks][j][1]);
        }
        // dump partials (row stride 104 -> conflict-free STS.64)
        {
            float* rw = sRed + wk * 1664;      // 16*104 per k-quarter
            int colb = wn * 48;
#pragma unroll
            for (int j = 0; j < 6; j++) {
                *(float2*)&rw[g * 104 + colb + j * 8 + 2 * q]       = make_float2(c[j][0], c[j][1]);
                *(float2*)&rw[(g + 8) * 104 + colb + j * 8 + 2 * q] = make_float2(c[j][2], c[j][3]);
            }
        }
        __syncthreads();

        // reduce (4 k-partials) + GRU pointwise; gates at cols uc / 32+uc / 64+uc
        float hv0, hv1;
        {
            int o = lr0 * 104;
            float gr = sRed[o + uc]      + sRed[1664 + o + uc]      + sRed[3328 + o + uc]      + sRed[4992 + o + uc];
            float gz = sRed[o + 32 + uc] + sRed[1664 + o + 32 + uc] + sRed[3328 + o + 32 + uc] + sRed[4992 + o + 32 + uc];
            float gn = sRed[o + 64 + uc] + sRed[1664 + o + 64 + uc] + sRed[3328 + o + 64 + uc] + sRed[4992 + o + 64 + uc];
            float rr = sigf(xr0 + gr + sBhh[uc]);
            float zz = sigf(xz0 + gz + sBhh[32 + uc]);
            float nn = tanhf(xn0 + rr * (gn + sBhh[64 + uc]));
            hv0 = (1.0f - zz) * nn + zz * hpc0;
        }
        {
            int o = lr1 * 104;
            float gr = sRed[o + uc]      + sRed[1664 + o + uc]      + sRed[3328 + o + uc]      + sRed[4992 + o + uc];
            float gz = sRed[o + 32 + uc] + sRed[1664 + o + 32 + uc] + sRed[3328 + o + 32 + uc] + sRed[4992 + o + 32 + uc];
            float gn = sRed[o + 64 + uc] + sRed[1664 + o + 64 + uc] + sRed[3328 + o + 64 + uc] + sRed[4992 + o + 64 + uc];
            float rr = sigf(xr1 + gr + sBhh[uc]);
            float zz = sigf(xz1 + gz + sBhh[32 + uc]);
            float nn = tanhf(xn1 + rr * (gn + sBhh[64 + uc]));
            hv1 = (1.0f - zz) * nn + zz * hpc1;
        }
        hpc0 = hv0; hpc1 = hv1;
        // publish next-h slice (must precede release)
        buf[(1 - par) * 4096 + lr0 * 256 + gu] = hv0;
        buf[(1 - par) * 4096 + lr1 * 256 + gu] = hv1;
        __syncthreads();                    // all buf writes ordered before release
        if (tid == 0) red_rel(cnt, 1u);

        // off-critical-path: streaming outputs + xi prefetch for t+1
        outp[row0 * 256 + gu] = hv0;
        outp[row1 * 256 + gu] = hv1;
        if (t + 1 < 1024) {
            int tt = dir ? (1023 - (t + 1)) : (t + 1);
            const float* x0 = xi + ((size_t)(bs * 16 + lr0) * 1024 + tt) * 768;
            const float* x1 = xi + ((size_t)(bs * 16 + lr1) * 1024 + tt) * 768;
            xr0 = x0[gu]; xz0 = x0[256 + gu]; xn0 = x0[512 + gu];
            xr1 = x1[gu]; xz1 = x1[256 + gu]; xn1 = x1[512 + gu];
        }

        target += 8u;
        while (ld_acq(cnt) < target) {}
    }
}

// ---------------- pooling: partial mean over S (4 chunks), both encodes ----------------
__global__ void pool_kernel() {
    int b = blockIdx.x, cch = blockIdx.y, d = threadIdx.x;
    const float* h0 = g_hn + ((size_t)b * 1024 + cch * 256) * 256 + d;
    const float* h1 = g_hn + ((size_t)(32 + b) * 1024 + cch * 256) * 256 + d;
    float s = 0.f;
#pragma unroll 4
    for (int si = 0; si < 256; si++) s += h0[(size_t)si * 256] + h1[(size_t)si * 256];
    g_pool[((size_t)cch * 32 + b) * 256 + d] = s;
}

// ---------------- head: proj to O=64, LN, exact GELU ----------------
__global__ void head_kernel(const float* __restrict__ pw, const float* __restrict__ pb,
                            const float* __restrict__ pg, const float* __restrict__ pbt,
                            float* __restrict__ out) {
    __shared__ float pooled[256];
    __shared__ float sp[64];
    int b = blockIdx.x, o = threadIdx.x;   // 64 threads
    for (int k = o; k < 256; k += 64) {
        float s = 0.f;
#pragma unroll
        for (int cch = 0; cch < 4; cch++) s += g_pool[((size_t)cch * 32 + b) * 256 + k];
        pooled[k] = s * (0.5f / 1024.0f);
    }
    __syncthreads();
    float acc = pb[o];
    for (int k = 0; k < 256; k++) acc += pooled[k] * pw[o * 256 + k];
    sp[o] = acc;
    __syncthreads();
    float m = 0.f;
    for (int k = 0; k < 64; k++) m += sp[k];
    m *= (1.0f / 64.0f);
    float v = 0.f;
    for (int k = 0; k < 64; k++) { float d = sp[k] - m; v += d * d; }
    v *= (1.0f / 64.0f);
    float y = (acc - m) * rsqrtf(v + 1e-5f) * pg[o] + pbt[o];
    out[b * 64 + o] = y * 0.5f * (1.0f + erff(y * 0.70710678118654752f));
}

// ---------------- launch ----------------
extern "C" void kernel_launch(void* const* d_in, const int* in_sizes, int n_in,
                              void* d_out, int out_size) {
    const int*   tok  = (const int*)  d_in[0];
    const float* emb  = (const float*)d_in[1];
    const float* pos  = (const float*)d_in[2];
    const float* lng  = (const float*)d_in[3];
    const float* lnb  = (const float*)d_in[4];
    const float* wihF = (const float*)d_in[5];
    const float* whhF = (const float*)d_in[6];
    const float* bihF = (const float*)d_in[7];
    const float* bhhF = (const float*)d_in[8];
    const float* wihR = (const float*)d_in[9];
    const float* whhR = (const float*)d_in[10];
    const float* bihR = (const float*)d_in[11];
    const float* bhhR = (const float*)d_in[12];
    const float* wg   = (const float*)d_in[13];
    const float* bg   = (const float*)d_in[14];
    const float* wo   = (const float*)d_in[15];
    const float* bo   = (const float*)d_in[16];
    const float* fng  = (const float*)d_in[17];
    const float* fnb  = (const float*)d_in[18];
    const float* pw   = (const float*)d_in[19];
    const float* pb   = (const float*)d_in[20];
    const float* plg  = (const float*)d_in[21];
    const float* plb  = (const float*)d_in[22];

    float* hf; float* hr; float* xif; float* xir; float* hnp; float* hp; void* cntp;
    cudaGetSymbolAddress((void**)&hf,  g_f);
    cudaGetSymbolAddress((void**)&hr,  g_r);
    cudaGetSymbolAddress((void**)&xif, g_xif);
    cudaGetSymbolAddress((void**)&xir, g_xir);
    cudaGetSymbolAddress((void**)&hnp, g_hn);
    cudaGetSymbolAddress((void**)&hp,  g_h);
    cudaGetSymbolAddress(&cntp, g_cnt);

    cudaFuncSetAttribute(rnn_kernel, cudaFuncAttributeMaxDynamicSharedMemorySize, RNN_SMEM);
    cudaFuncSetAttribute(gemm_kernel<0>, cudaFuncAttributeMaxDynamicSharedMemorySize, GEMM_SMEM);
    cudaFuncSetAttribute(gemm_kernel<1>, cudaFuncAttributeMaxDynamicSharedMemorySize, GEMM_SMEM);
    cudaFuncSetAttribute(gemm_kernel<2>, cudaFuncAttributeMaxDynamicSharedMemorySize, GEMM_SMEM);

    embed_kernel<<<65536, 256>>>(tok, emb, pos);

    for (int i = 0; i < 4; i++) {
        const float* wihFi = wihF + (size_t)i * 768 * 256;
        const float* whhFi = whhF + (size_t)i * 768 * 256;
        const float* bihFi = bihF + (size_t)i * 768;
        const float* bhhFi = bhhF + (size_t)i * 768;
        const float* wihRi = wihR + (size_t)i * 768 * 256;
        const float* whhRi = whhR + (size_t)i * 768 * 256;
        const float* bihRi = bihR + (size_t)i * 768;
        const float* bhhRi = bhhR + (size_t)i * 768;
        const float* wgi   = wg + (size_t)i * 256 * 512;
        const float* bgi   = bg + (size_t)i * 256;
        const float* woi   = wo + (size_t)i * 256 * 256;
        const float* boi   = bo + (size_t)i * 256;

        ln_kernel<<<8192, 256>>>(hp, lng + i * 256, lnb + i * 256, hnp);
        gemm_kernel<0><<<dim3(12, 512), 256, GEMM_SMEM>>>(hnp, nullptr, wihFi, bihFi, xif);
        gemm_kernel<0><<<dim3(12, 512), 256, GEMM_SMEM>>>(hnp, nullptr, wihRi, bihRi, xir);
        cudaMemsetAsync(cntp, 0, 8 * 64 * sizeof(unsigned));
        rnn_kernel<<<64, 256, RNN_SMEM>>>(whhFi, whhRi, bhhFi, bhhRi);
        gemm_kernel<1><<<dim3(4, 512), 256, GEMM_SMEM>>>(hf, hr, wgi, bgi, hnp);     // hn <- gated c
        gemm_kernel<2><<<dim3(4, 512), 256, GEMM_SMEM>>>(hnp, nullptr, woi, boi, hp); // h += c@wo^T+bo
    }

    ln_kernel<<<8192, 256>>>(hp, fng, fnb, hnp);
    pool_kernel<<<dim3(32, 4), 256>>>();
    head_kernel<<<32, 64>>>(pw, pb, plg, plb, (float*)d_out);
}

// round 12
// speedup vs baseline: 1.0524x; 1.0524x over previous
#include <cuda_runtime.h>
#include <cuda_bf16.h>
#include <cstdint>
#include <cstddef>

// Problem dims: B=32, S=1024, D=256, L=4, O=64, V=5. Two encodes -> 64 seqs.
#define NROWS 65536          // 2 * 32 * 1024

// ---------------- device scratch (static; no runtime allocation) ----------------
__device__ float g_h  [(size_t)NROWS * 256];   // residual stream
__device__ float g_hn [(size_t)NROWS * 256];   // LN out / gated "c"
__device__ float g_f  [(size_t)NROWS * 256];   // forward GRU out
__device__ float g_r  [(size_t)NROWS * 256];   // reverse GRU out (natural time order)
__device__ float g_xif[(size_t)NROWS * 768];   // xi forward
__device__ float g_xir[(size_t)NROWS * 768];   // xi reverse
__device__ float g_pool[4 * 32 * 256];         // [s-chunk][batch][d] partial sums
__device__ float2 g_stats[NROWS];              // final-LN per-row (mean, rstd)
__device__ float g_hbuf[8 * 2 * 16 * 256];     // [group][parity][row16][unit256]
__device__ unsigned g_cnt[8 * 64];             // one counter per 256B

// ---------------- helpers ----------------
__device__ __forceinline__ unsigned f2tfu(float x) {
    unsigned u; asm("cvt.rna.tf32.f32 %0, %1;" : "=r"(u) : "f"(x)); return u;
}
__device__ __forceinline__ float f2tff(float x) {
    return __uint_as_float(f2tfu(x));
}
__device__ __forceinline__ void mma_tf32(float* c, const unsigned* a, unsigned b0, unsigned b1) {
    asm volatile(
        "mma.sync.aligned.m16n8k8.row.col.f32.tf32.tf32.f32 "
        "{%0,%1,%2,%3}, {%4,%5,%6,%7}, {%8,%9}, {%0,%1,%2,%3};\n"
        : "+f"(c[0]), "+f"(c[1]), "+f"(c[2]), "+f"(c[3])
        : "r"(a[0]), "r"(a[1]), "r"(a[2]), "r"(a[3]), "r"(b0), "r"(b1));
}
__device__ __forceinline__ unsigned ld_acq(const unsigned* p) {
    unsigned v; asm volatile("ld.global.acquire.gpu.u32 %0, [%1];" : "=r"(v) : "l"(p)); return v;
}
__device__ __forceinline__ void red_rel(unsigned* p, unsigned v) {
    asm volatile("red.release.gpu.global.add.u32 [%0], %1;" :: "l"(p), "r"(v) : "memory");
}
__device__ __forceinline__ float sigf(float x) { return 1.0f / (1.0f + expf(-x)); }
__device__ __forceinline__ void cp16(void* s, const void* gp) {
    unsigned sa = (unsigned)__cvta_generic_to_shared(s);
    asm volatile("cp.async.cg.shared.global [%0], [%1], 16;\n" :: "r"(sa), "l"(gp));
}
__device__ __forceinline__ void cp_commit() { asm volatile("cp.async.commit_group;\n"); }
template <int N> __device__ __forceinline__ void cp_wait() {
    asm volatile("cp.async.wait_group %0;\n" :: "n"(N));
}

// ---------------- embedding (both encodes) ----------------
__global__ void embed_kernel(const int* __restrict__ tok, const float* __restrict__ emb,
                             const float* __restrict__ pos) {
    int bid = blockIdx.x;
    int d = threadIdx.x;
    int e = bid >> 15, rem = bid & 32767, b = rem >> 10, s = rem & 1023;
    int t;
    if (e == 0) t = tok[b * 1024 + s];
    else { int t0 = tok[b * 1024 + (1023 - s)]; t = (t0 < 4) ? (3 - t0) : 4; }
    g_h[(size_t)bid * 256 + d] = emb[t * 256 + d] + pos[s * 256 + d];
}

// ---------------- layernorm over D=256 (one warp per row, 8 rows per CTA) ----------------
__global__ void ln_kernel(const float* __restrict__ X, const float* __restrict__ gw,
                          const float* __restrict__ gb, float* __restrict__ Y) {
    int warp = threadIdx.x >> 5, lane = threadIdx.x & 31;
    int row = blockIdx.x * 8 + warp;
    const float* x = X + (size_t)row * 256;
    float v[8];
#pragma unroll
    for (int i = 0; i < 8; i++) v[i] = x[lane + i * 32];
    float s = 0.f;
#pragma unroll
    for (int i = 0; i < 8; i++) s += v[i];
#pragma unroll
    for (int o = 16; o > 0; o >>= 1) s += __shfl_xor_sync(0xffffffffu, s, o);
    float m = s * (1.0f / 256.0f);
    float q = 0.f;
#pragma unroll
    for (int i = 0; i < 8; i++) { float d = v[i] - m; q += d * d; }
#pragma unroll
    for (int o = 16; o > 0; o >>= 1) q += __shfl_xor_sync(0xffffffffu, q, o);
    float rs = rsqrtf(q * (1.0f / 256.0f) + 1e-5f);
    float* y = Y + (size_t)row * 256;
#pragma unroll
    for (int i = 0; i < 8; i++) {
        int d = lane + i * 32;
        y[d] = (v[i] - m) * rs * gw[d] + gb[d];
    }
}

// ---------------- final-LN stats only (mean, rstd per row) ----------------
__global__ void ln_stats_kernel(const float* __restrict__ X) {
    int warp = threadIdx.x >> 5, lane = threadIdx.x & 31;
    int row = blockIdx.x * 8 + warp;
    const float* x = X + (size_t)row * 256;
    float v[8];
#pragma unroll
    for (int i = 0; i < 8; i++) v[i] = x[lane + i * 32];
    float s = 0.f;
#pragma unroll
    for (int i = 0; i < 8; i++) s += v[i];
#pragma unroll
    for (int o = 16; o > 0; o >>= 1) s += __shfl_xor_sync(0xffffffffu, s, o);
    float m = s * (1.0f / 256.0f);
    float q = 0.f;
#pragma unroll
    for (int i = 0; i < 8; i++) { float d = v[i] - m; q += d * d; }
#pragma unroll
    for (int o = 16; o > 0; o >>= 1) q += __shfl_xor_sync(0xffffffffu, q, o);
    float rs = rsqrtf(q * (1.0f / 256.0f) + 1e-5f);
    if (lane == 0) g_stats[row] = make_float2(m, rs);
}

// ---------------- tf32 GEMM with cp.async 2-stage pipeline ----------------
// MODE 1: gate (K=512: k<256 from A=f, k>=256 from A2=r; N=256; out = g*f+(1-g)*r)
// MODE 2: oproj(K=256, N=256; out += val + bias  (residual))
#define GEMM_SMEM (2 * (128 * 36 + 64 * 36) * 4)

template <int MODE>
__global__ __launch_bounds__(256)
void gemm_kernel(const float* __restrict__ A, const float* __restrict__ A2,
                 const float* __restrict__ W, const float* __restrict__ bias,
                 float* __restrict__ out) {
    extern __shared__ float smg[];
    float* sAb = smg;                  // 2 x 128 x 36
    float* sBb = smg + 2 * 128 * 36;   // 2 x 64 x 36
    const int KT  = (MODE == 1) ? 512 : 256;
    const int WLD = (MODE == 1) ? 512 : 256;
    const int NIT = KT / 32;
    int tid = threadIdx.x, lane = tid & 31, warp = tid >> 5;
    int wm = warp >> 1, wn = warp & 1;
    int rowBase = blockIdx.y * 128;
    int colBase = blockIdx.x * 64;
    int g = lane >> 2, q = lane & 3;

    float acc[2][4][4];
#pragma unroll
    for (int a = 0; a < 2; a++)
#pragma unroll
        for (int b = 0; b < 4; b++)
#pragma unroll
            for (int c = 0; c < 4; c++) acc[a][b][c] = 0.f;

    auto stage = [&](int bsel, int k0) {
        const float* Asrc = (MODE == 1 && k0 >= 256) ? A2 : A;
        int kA = (MODE == 1) ? (k0 & 255) : k0;
        float* dA = sAb + bsel * 128 * 36;
#pragma unroll
        for (int i = 0; i < 4; i++) {
            int flat = tid + i * 256;
            int r = flat >> 3, c4 = flat & 7;
            cp16(&dA[r * 36 + c4 * 4], &Asrc[(size_t)(rowBase + r) * 256 + kA + c4 * 4]);
        }
        float* dB = sBb + bsel * 64 * 36;
#pragma unroll
        for (int i = 0; i < 2; i++) {
            int flat = tid + i * 256;
            int r = flat >> 3, c4 = flat & 7;
            cp16(&dB[r * 36 + c4 * 4], &W[(size_t)(colBase + r) * WLD + k0 + c4 * 4]);
        }
    };

    stage(0, 0); cp_commit();
    for (int it = 0; it < NIT; it++) {
        if (it + 1 < NIT) { stage((it + 1) & 1, (it + 1) * 32); cp_commit(); cp_wait<1>(); }
        else cp_wait<0>();
        __syncthreads();
        const float* sA = sAb + (it & 1) * 128 * 36;
        const float* sB = sBb + (it & 1) * 64 * 36;
#pragma unroll
        for (int kk = 0; kk < 4; kk++) {
            int ko = kk * 8;
            unsigned a[2][4];
#pragma unroll
            for (int mt = 0; mt < 2; mt++) {
                int rb2 = wm * 32 + mt * 16;
                a[mt][0] = __float_as_uint(sA[(rb2 + g) * 36 + ko + q]);
                a[mt][1] = __float_as_uint(sA[(rb2 + g + 8) * 36 + ko + q]);
                a[mt][2] = __float_as_uint(sA[(rb2 + g) * 36 + ko + q + 4]);
                a[mt][3] = __float_as_uint(sA[(rb2 + g + 8) * 36 + ko + q + 4]);
            }
#pragma unroll
            for (int nt = 0; nt < 4; nt++) {
                int nb = wn * 32 + nt * 8;
                unsigned b0 = __float_as_uint(sB[(nb + g) * 36 + ko + q]);
                unsigned b1 = __float_as_uint(sB[(nb + g) * 36 + ko + q + 4]);
                mma_tf32(acc[0][nt], a[0], b0, b1);
                mma_tf32(acc[1][nt], a[1], b0, b1);
            }
        }
        __syncthreads();
    }
#pragma unroll
    for (int mt = 0; mt < 2; mt++)
#pragma unroll
        for (int nt = 0; nt < 4; nt++)
#pragma unroll
            for (int i = 0; i < 4; i++) {
                int row = rowBase + wm * 32 + mt * 16 + g + ((i & 2) ? 8 : 0);
                int coln = colBase + wn * 32 + nt * 8 + 2 * q + (i & 1);
                float val = acc[mt][nt][i] + bias[coln];
                if (MODE == 1) {
                    float gg = sigf(val);
                    float fv = A [(size_t)row * 256 + coln];
                    float rv = A2[(size_t)row * 256 + coln];
                    out[(size_t)row * 256 + coln] = gg * fv + (1.0f - gg) * rv;
                } else {
                    out[(size_t)row * 256 + coln] += val;
                }
            }
}

// ---------------- merged xi GEMM (F + R in one launch): K=256, N=768 each ----------------
__global__ __launch_bounds__(256)
void xi_kernel(const float* __restrict__ A,
               const float* __restrict__ Wf, const float* __restrict__ Wr,
               const float* __restrict__ bf, const float* __restrict__ br,
               float* __restrict__ outF, float* __restrict__ outR) {
    extern __shared__ float smg[];
    float* sAb = smg;
    float* sBb = smg + 2 * 128 * 36;
    bool rev = blockIdx.x >= 12;
    const float* W    = rev ? Wr : Wf;
    const float* bias = rev ? br : bf;
    float* out        = rev ? outR : outF;
    int colBase = (rev ? (int)blockIdx.x - 12 : (int)blockIdx.x) * 64;
    int rowBase = blockIdx.y * 128;
    int tid = threadIdx.x, lane = tid & 31, warp = tid >> 5;
    int wm = warp >> 1, wn = warp & 1;
    int g = lane >> 2, q = lane & 3;

    float acc[2][4][4];
#pragma unroll
    for (int a = 0; a < 2; a++)
#pragma unroll
        for (int b = 0; b < 4; b++)
#pragma unroll
            for (int c = 0; c < 4; c++) acc[a][b][c] = 0.f;

    auto stage = [&](int bsel, int k0) {
        float* dA = sAb + bsel * 128 * 36;
#pragma unroll
        for (int i = 0; i < 4; i++) {
            int flat = tid + i * 256;
            int r = flat >> 3, c4 = flat & 7;
            cp16(&dA[r * 36 + c4 * 4], &A[(size_t)(rowBase + r) * 256 + k0 + c4 * 4]);
        }
        float* dB = sBb + bsel * 64 * 36;
#pragma unroll
        for (int i = 0; i < 2; i++) {
            int flat = tid + i * 256;
            int r = flat >> 3, c4 = flat & 7;
            cp16(&dB[r * 36 + c4 * 4], &W[(size_t)(colBase + r) * 256 + k0 + c4 * 4]);
        }
    };

    stage(0, 0); cp_commit();
    for (int it = 0; it < 8; it++) {
        if (it + 1 < 8) { stage((it + 1) & 1, (it + 1) * 32); cp_commit(); cp_wait<1>(); }
        else cp_wait<0>();
        __syncthreads();
        const float* sA = sAb + (it & 1) * 128 * 36;
        const float* sB = sBb + (it & 1) * 64 * 36;
#pragma unroll
        for (int kk = 0; kk < 4; kk++) {
            int ko = kk * 8;
            unsigned a[2][4];
#pragma unroll
            for (int mt = 0; mt < 2; mt++) {
                int rb2 = wm * 32 + mt * 16;
                a[mt][0] = __float_as_uint(sA[(rb2 + g) * 36 + ko + q]);
                a[mt][1] = __float_as_uint(sA[(rb2 + g + 8) * 36 + ko + q]);
                a[mt][2] = __float_as_uint(sA[(rb2 + g) * 36 + ko + q + 4]);
                a[mt][3] = __float_as_uint(sA[(rb2 + g + 8) * 36 + ko + q + 4]);
            }
#pragma unroll
            for (int nt = 0; nt < 4; nt++) {
                int nb = wn * 32 + nt * 8;
                unsigned b0 = __float_as_uint(sB[(nb + g) * 36 + ko + q]);
                unsigned b1 = __float_as_uint(sB[(nb + g) * 36 + ko + q + 4]);
                mma_tf32(acc[0][nt], a[0], b0, b1);
                mma_tf32(acc[1][nt], a[1], b0, b1);
            }
        }
        __syncthreads();
    }
#pragma unroll
    for (int mt = 0; mt < 2; mt++)
#pragma unroll
        for (int nt = 0; nt < 4; nt++)
#pragma unroll
            for (int i = 0; i < 4; i++) {
                int row = rowBase + wm * 32 + mt * 16 + g + ((i & 2) ? 8 : 0);
                int coln = colBase + wn * 32 + nt * 8 + 2 * q + (i & 1);
                out[(size_t)row * 768 + coln] = acc[mt][nt][i] + bias[coln];
            }
}

// ---------------- persistent bidirectional GRU scan (R8-proven config) ----------------
// 128 CTAs: dir(2) x batch-slice(4, 16 rows) x unit-slice(16, 16 hidden units).
#define RNN_SMEM ((48*260 + 16*260 + 4*16*48 + 48) * 4)

__global__ __launch_bounds__(128)
void rnn_kernel(const float* __restrict__ whhF, const float* __restrict__ whhR,
                const float* __restrict__ bhhF, const float* __restrict__ bhhR) {
    extern __shared__ float sm[];
    float* sW   = sm;                 // 48 x 260 (tf32)  [init only]
    float* sH   = sW + 48 * 260;      // 16 x 260 (tf32 h tile)
    float* sRed = sH + 16 * 260;      // 4 warps x 16 x 48 partials
    float* sBhh = sRed + 4 * 16 * 48; // 48

    int cta = blockIdx.x;
    int dir = cta >> 6, rem = cta & 63, bs = rem >> 4, u = rem & 15;
    int group = dir * 4 + bs;
    const float* W    = dir ? whhR : whhF;
    const float* bhh  = dir ? bhhR : bhhF;
    const float* xi   = dir ? g_xir : g_xif;
    float*       outp = dir ? g_r   : g_f;
    float*    buf = g_hbuf + (size_t)group * 8192;   // 2 x 16 x 256
    unsigned* cnt = &g_cnt[group * 64];

    int tid = threadIdx.x, lane = tid & 31, warp = tid >> 5;
    int g = lane >> 2, q = lane & 3;

    for (int idx = tid; idx < 48 * 256; idx += 128) {
        int rI = idx >> 8, k = idx & 255;
        int grow = (rI >> 4) * 256 + u * 16 + (rI & 15);
        sW[rI * 260 + k] = f2tff(W[(size_t)grow * 256 + k]);
    }
    if (tid < 48) {
        int grow = (tid >> 4) * 256 + u * 16 + (tid & 15);
        sBhh[tid] = bhh[grow];
    }
    for (int idx = tid; idx < 256; idx += 128) {
        int lr = idx >> 4, c = idx & 15;
        buf[lr * 256 + u * 16 + c] = 0.f;
    }
    __syncthreads();

    int kbase = warp * 64;
    unsigned bfr[8][6][2];
#pragma unroll
    for (int ks = 0; ks < 8; ks++) {
        int k0 = kbase + ks * 8;
#pragma unroll
        for (int j = 0; j < 6; j++) {
            bfr[ks][j][0] = __float_as_uint(sW[(j * 8 + g) * 260 + k0 + q]);
            bfr[ks][j][1] = __float_as_uint(sW[(j * 8 + g) * 260 + k0 + q + 4]);
        }
    }

    if (tid == 0) red_rel(cnt, 1u);
    unsigned target = 16u;
    if (tid == 0) { while (ld_acq(cnt) < target) {} }
    __syncthreads();

    int uc = tid & 15;
    int gu = u * 16 + uc;
    int lr0 = tid >> 4;
    int lr1 = lr0 + 8;

    float xr0, xz0, xn0, xr1, xz1, xn1;
    {
        int tt = dir ? 1023 : 0;
        const float* x0 = xi + ((size_t)(bs * 16 + lr0) * 1024 + tt) * 768;
        const float* x1 = xi + ((size_t)(bs * 16 + lr1) * 1024 + tt) * 768;
        xr0 = x0[gu]; xz0 = x0[256 + gu]; xn0 = x0[512 + gu];
        xr1 = x1[gu]; xz1 = x1[256 + gu]; xn1 = x1[512 + gu];
    }

    for (int t = 0; t < 1024; t++) {
        int par = t & 1;
        int ttime = dir ? (1023 - t) : t;
        size_t row0 = (size_t)(bs * 16 + lr0) * 1024 + ttime;
        size_t row1 = (size_t)(bs * 16 + lr1) * 1024 + ttime;

        float hp0 = buf[par * 4096 + lr0 * 256 + gu];
        float hp1 = buf[par * 4096 + lr1 * 256 + gu];

#pragma unroll
        for (int it = 0; it < 8; it++) {
            int idx = tid + it * 128;
            int lr = idx >> 6, c4 = idx & 63;
            float4 v = *(const float4*)&buf[par * 4096 + lr * 256 + c4 * 4];
            float4 w;
            w.x = f2tff(v.x); w.y = f2tff(v.y); w.z = f2tff(v.z); w.w = f2tff(v.w);
            *(float4*)&sH[lr * 260 + c4 * 4] = w;
        }
        __syncthreads();

        float c[6][4];
#pragma unroll
        for (int j = 0; j < 6; j++)
#pragma unroll
            for (int i = 0; i < 4; i++) c[j][i] = 0.f;
#pragma unroll
        for (int ks = 0; ks < 8; ks++) {
            int k0 = kbase + ks * 8;
            unsigned a[4];
            a[0] = __float_as_uint(sH[g * 260 + k0 + q]);
            a[1] = __float_as_uint(sH[(g + 8) * 260 + k0 + q]);
            a[2] = __float_as_uint(sH[g * 260 + k0 + q + 4]);
            a[3] = __float_as_uint(sH[(g + 8) * 260 + k0 + q + 4]);
#pragma unroll
            for (int j = 0; j < 6; j++)
                mma_tf32(c[j], a, bfr[ks][j][0], bfr[ks][j][1]);
        }
        {
            float* rw = sRed + warp * 768;
#pragma unroll
            for (int j = 0; j < 6; j++) {
                *(float2*)&rw[g * 48 + j * 8 + 2 * q]       = make_float2(c[j][0], c[j][1]);
                *(float2*)&rw[(g + 8) * 48 + j * 8 + 2 * q] = make_float2(c[j][2], c[j][3]);
            }
        }
        __syncthreads();

        float hv0, hv1;
        {
            int o = lr0 * 48;
            float gr = sRed[o + uc]      + sRed[768 + o + uc]      + sRed[1536 + o + uc]      + sRed[2304 + o + uc];
            float gz = sRed[o + 16 + uc] + sRed[768 + o + 16 + uc] + sRed[1536 + o + 16 + uc] + sRed[2304 + o + 16 + uc];
            float gn = sRed[o + 32 + uc] + sRed[768 + o + 32 + uc] + sRed[1536 + o + 32 + uc] + sRed[2304 + o + 32 + uc];
            float rr = sigf(xr0 + gr + sBhh[uc]);
            float zz = sigf(xz0 + gz + sBhh[16 + uc]);
            float nn = tanhf(xn0 + rr * (gn + sBhh[32 + uc]));
            hv0 = (1.0f - zz) * nn + zz * hp0;
        }
        {
            int o = lr1 * 48;
            float gr = sRed[o + uc]      + sRed[768 + o + uc]      + sRed[1536 + o + uc]      + sRed[2304 + o + uc];
            float gz = sRed[o + 16 + uc] + sRed[768 + o + 16 + uc] + sRed[1536 + o + 16 + uc] + sRed[2304 + o + 16 + uc];
            float gn = sRed[o + 32 + uc] + sRed[768 + o + 32 + uc] + sRed[1536 + o + 32 + uc] + sRed[2304 + o + 32 + uc];
            float rr = sigf(xr1 + gr + sBhh[uc]);
            float zz = sigf(xz1 + gz + sBhh[16 + uc]);
            float nn = tanhf(xn1 + rr * (gn + sBhh[32 + uc]));
            hv1 = (1.0f - zz) * nn + zz * hp1;
        }
        buf[(1 - par) * 4096 + lr0 * 256 + gu] = hv0;
        buf[(1 - par) * 4096 + lr1 * 256 + gu] = hv1;
        __syncthreads();
        if (tid == 0) red_rel(cnt, 1u);

        if (t + 1 < 1024) {
            int tt = dir ? (1023 - (t + 1)) : (t + 1);
            const float* x0 = xi + ((size_t)(bs * 16 + lr0) * 1024 + tt) * 768;
            const float* x1 = xi + ((size_t)(bs * 16 + lr1) * 1024 + tt) * 768;
            xr0 = x0[gu]; xz0 = x0[256 + gu]; xn0 = x0[512 + gu];
            xr1 = x1[gu]; xz1 = x1[256 + gu]; xn1 = x1[512 + gu];
        }
        outp[row0 * 256 + gu] = hv0;
        outp[row1 * 256 + gu] = hv1;

        target += 16u;
        if (tid == 0) { while (ld_acq(cnt) < target) {} }
        __syncthreads();
    }
}

// ---------------- pooling: partial sum of (h-m)*rs over S chunks, both encodes ----------------
__global__ void pool_kernel() {
    int b = blockIdx.x, cch = blockIdx.y, d = threadIdx.x;
    size_t r0 = (size_t)b * 1024 + cch * 256;
    size_t r1 = (size_t)(32 + b) * 1024 + cch * 256;
    const float* h0 = g_h + r0 * 256 + d;
    const float* h1 = g_h + r1 * 256 + d;
    float s = 0.f;
#pragma unroll 4
    for (int si = 0; si < 256; si++) {
        float2 a = g_stats[r0 + si];
        float2 c = g_stats[r1 + si];
        s += (h0[(size_t)si * 256] - a.x) * a.y + (h1[(size_t)si * 256] - c.x) * c.y;
    }
    g_pool[((size_t)cch * 32 + b) * 256 + d] = s;
}

// ---------------- head: apply final-LN gain/bias to pooled, proj O=64, LN, GELU ----------------
__global__ void head_kernel(const float* __restrict__ fng, const float* __restrict__ fnb,
                            const float* __restrict__ pw, const float* __restrict__ pb,
                            const float* __restrict__ pg, const float* __restrict__ pbt,
                            float* __restrict__ out) {
    __shared__ float pooled[256];
    __shared__ float sp[64];
    int b = blockIdx.x, o = threadIdx.x;   // 64 threads
    for (int k = o; k < 256; k += 64) {
        float s = 0.f;
#pragma unroll
        for (int cch = 0; cch < 4; cch++) s += g_pool[((size_t)cch * 32 + b) * 256 + k];
        pooled[k] = s * (0.5f / 1024.0f) * fng[k] + fnb[k];
    }
    __syncthreads();
    float acc = pb[o];
    for (int k = 0; k < 256; k++) acc += pooled[k] * pw[o * 256 + k];
    sp[o] = acc;
    __syncthreads();
    float m = 0.f;
    for (int k = 0; k < 64; k++) m += sp[k];
    m *= (1.0f / 64.0f);
    float v = 0.f;
    for (int k = 0; k < 64; k++) { float d = sp[k] - m; v += d * d; }
    v *= (1.0f / 64.0f);
    float y = (acc - m) * rsqrtf(v + 1e-5f) * pg[o] + pbt[o];
    out[b * 64 + o] = y * 0.5f * (1.0f + erff(y * 0.70710678118654752f));
}

// ---------------- launch ----------------
extern "C" void kernel_launch(void* const* d_in, const int* in_sizes, int n_in,
                              void* d_out, int out_size) {
    const int*   tok  = (const int*)  d_in[0];
    const float* emb  = (const float*)d_in[1];
    const float* pos  = (const float*)d_in[2];
    const float* lng  = (const float*)d_in[3];
    const float* lnb  = (const float*)d_in[4];
    const float* wihF = (const float*)d_in[5];
    const float* whhF = (const float*)d_in[6];
    const float* bihF = (const float*)d_in[7];
    const float* bhhF = (const float*)d_in[8];
    const float* wihR = (const float*)d_in[9];
    const float* whhR = (const float*)d_in[10];
    const float* bihR = (const float*)d_in[11];
    const float* bhhR = (const float*)d_in[12];
    const float* wg   = (const float*)d_in[13];
    const float* bg   = (const float*)d_in[14];
    const float* wo   = (const float*)d_in[15];
    const float* bo   = (const float*)d_in[16];
    const float* fng  = (const float*)d_in[17];
    const float* fnb  = (const float*)d_in[18];
    const float* pw   = (const float*)d_in[19];
    const float* pb   = (const float*)d_in[20];
    const float* plg  = (const float*)d_in[21];
    const float* plb  = (const float*)d_in[22];

    float* hf; float* hr; float* xif; float* xir; float* hnp; float* hp; void* cntp;
    cudaGetSymbolAddress((void**)&hf,  g_f);
    cudaGetSymbolAddress((void**)&hr,  g_r);
    cudaGetSymbolAddress((void**)&xif, g_xif);
    cudaGetSymbolAddress((void**)&xir, g_xir);
    cudaGetSymbolAddress((void**)&hnp, g_hn);
    cudaGetSymbolAddress((void**)&hp,  g_h);
    cudaGetSymbolAddress(&cntp, g_cnt);

    cudaFuncSetAttribute(rnn_kernel, cudaFuncAttributeMaxDynamicSharedMemorySize, RNN_SMEM);
    cudaFuncSetAttribute(xi_kernel, cudaFuncAttributeMaxDynamicSharedMemorySize, GEMM_SMEM);
    cudaFuncSetAttribute(gemm_kernel<1>, cudaFuncAttributeMaxDynamicSharedMemorySize, GEMM_SMEM);
    cudaFuncSetAttribute(gemm_kernel<2>, cudaFuncAttributeMaxDynamicSharedMemorySize, GEMM_SMEM);

    embed_kernel<<<65536, 256>>>(tok, emb, pos);

    for (int i = 0; i < 4; i++) {
        const float* wihFi = wihF + (size_t)i * 768 * 256;
        const float* whhFi = whhF + (size_t)i * 768 * 256;
        const float* bihFi = bihF + (size_t)i * 768;
        const float* bhhFi = bhhF + (size_t)i * 768;
        const float* wihRi = wihR + (size_t)i * 768 * 256;
        const float* whhRi = whhR + (size_t)i * 768 * 256;
        const float* bihRi = bihR + (size_t)i * 768;
        const float* bhhRi = bhhR + (size_t)i * 768;
        const float* wgi   = wg + (size_t)i * 256 * 512;
        const float* bgi   = bg + (size_t)i * 256;
        const float* woi   = wo + (size_t)i * 256 * 256;
        const float* boi   = bo + (size_t)i * 256;

        ln_kernel<<<8192, 256>>>(hp, lng + i * 256, lnb + i * 256, hnp);
        xi_kernel<<<dim3(24, 512), 256, GEMM_SMEM>>>(hnp, wihFi, wihRi, bihFi, bihRi, xif, xir);
        cudaMemsetAsync(cntp, 0, 8 * 64 * sizeof(unsigned));
        rnn_kernel<<<128, 128, RNN_SMEM>>>(whhFi, whhRi, bhhFi, bhhRi);
        gemm_kernel<1><<<dim3(4, 512), 256, GEMM_SMEM>>>(hf, hr, wgi, bgi, hnp);      // hn <- gated c
        gemm_kernel<2><<<dim3(4, 512), 256, GEMM_SMEM>>>(hnp, nullptr, woi, boi, hp); // h += c@wo^T+bo
    }

    ln_stats_kernel<<<8192, 256>>>(hp);
    pool_kernel<<<dim3(32, 4), 256>>>();
    head_kernel<<<32, 64>>>(fng, fnb, pw, pb, plg, plb, (float*)d_out);
}

// round 13
// speedup vs baseline: 1.0724x; 1.0190x over previous
#include <cuda_runtime.h>
#include <cuda_bf16.h>
#include <cstdint>
#include <cstddef>

// Problem dims: B=32, S=1024, D=256, L=4, O=64, V=5. Two encodes -> 64 seqs.
#define NROWS 65536          // 2 * 32 * 1024

// ---------------- device scratch (static; no runtime allocation) ----------------
__device__ float g_h  [(size_t)NROWS * 256];   // residual stream
__device__ float g_hn [(size_t)NROWS * 256];   // LN out / gated "c"
__device__ float g_f  [(size_t)NROWS * 256];   // forward GRU out
__device__ float g_r  [(size_t)NROWS * 256];   // reverse GRU out (natural time order)
__device__ float g_xif[(size_t)NROWS * 768];   // xi forward
__device__ float g_xir[(size_t)NROWS * 768];   // xi reverse
__device__ float g_pool[4 * 32 * 256];         // [s-chunk][batch][d] partial sums
__device__ float2 g_stats[NROWS];              // final-LN per-row (mean, rstd)
__device__ float g_hbuf[8 * 2 * 16 * 256];     // [group][parity][row16][unit256]
__device__ unsigned g_cnt[8 * 64];             // one counter per 256B

// ---------------- helpers ----------------
__device__ __forceinline__ unsigned f2tfu(float x) {
    unsigned u; asm("cvt.rna.tf32.f32 %0, %1;" : "=r"(u) : "f"(x)); return u;
}
__device__ __forceinline__ float f2tff(float x) {
    return __uint_as_float(f2tfu(x));
}
__device__ __forceinline__ void mma_tf32(float* c, const unsigned* a, unsigned b0, unsigned b1) {
    asm volatile(
        "mma.sync.aligned.m16n8k8.row.col.f32.tf32.tf32.f32 "
        "{%0,%1,%2,%3}, {%4,%5,%6,%7}, {%8,%9}, {%0,%1,%2,%3};\n"
        : "+f"(c[0]), "+f"(c[1]), "+f"(c[2]), "+f"(c[3])
        : "r"(a[0]), "r"(a[1]), "r"(a[2]), "r"(a[3]), "r"(b0), "r"(b1));
}
__device__ __forceinline__ unsigned ld_acq(const unsigned* p) {
    unsigned v; asm volatile("ld.global.acquire.gpu.u32 %0, [%1];" : "=r"(v) : "l"(p)); return v;
}
__device__ __forceinline__ void red_rel(unsigned* p, unsigned v) {
    asm volatile("red.release.gpu.global.add.u32 [%0], %1;" :: "l"(p), "r"(v) : "memory");
}
__device__ __forceinline__ float sigf(float x) { return 1.0f / (1.0f + expf(-x)); }
__device__ __forceinline__ void cp16(void* s, const void* gp) {
    unsigned sa = (unsigned)__cvta_generic_to_shared(s);
    asm volatile("cp.async.cg.shared.global [%0], [%1], 16;\n" :: "r"(sa), "l"(gp));
}
__device__ __forceinline__ void cp_commit() { asm volatile("cp.async.commit_group;\n"); }
template <int N> __device__ __forceinline__ void cp_wait() {
    asm volatile("cp.async.wait_group %0;\n" :: "n"(N));
}

// ---------------- embedding (both encodes) ----------------
__global__ void embed_kernel(const int* __restrict__ tok, const float* __restrict__ emb,
                             const float* __restrict__ pos) {
    int bid = blockIdx.x;
    int d = threadIdx.x;
    int e = bid >> 15, rem = bid & 32767, b = rem >> 10, s = rem & 1023;
    int t;
    if (e == 0) t = tok[b * 1024 + s];
    else { int t0 = tok[b * 1024 + (1023 - s)]; t = (t0 < 4) ? (3 - t0) : 4; }
    g_h[(size_t)bid * 256 + d] = emb[t * 256 + d] + pos[s * 256 + d];
}

// ---------------- layernorm over D=256 (one warp per row, 8 rows per CTA) ----------------
__global__ void ln_kernel(const float* __restrict__ X, const float* __restrict__ gw,
                          const float* __restrict__ gb, float* __restrict__ Y) {
    int warp = threadIdx.x >> 5, lane = threadIdx.x & 31;
    int row = blockIdx.x * 8 + warp;
    const float* x = X + (size_t)row * 256;
    float v[8];
#pragma unroll
    for (int i = 0; i < 8; i++) v[i] = x[lane + i * 32];
    float s = 0.f;
#pragma unroll
    for (int i = 0; i < 8; i++) s += v[i];
#pragma unroll
    for (int o = 16; o > 0; o >>= 1) s += __shfl_xor_sync(0xffffffffu, s, o);
    float m = s * (1.0f / 256.0f);
    float q = 0.f;
#pragma unroll
    for (int i = 0; i < 8; i++) { float d = v[i] - m; q += d * d; }
#pragma unroll
    for (int o = 16; o > 0; o >>= 1) q += __shfl_xor_sync(0xffffffffu, q, o);
    float rs = rsqrtf(q * (1.0f / 256.0f) + 1e-5f);
    float* y = Y + (size_t)row * 256;
#pragma unroll
    for (int i = 0; i < 8; i++) {
        int d = lane + i * 32;
        y[d] = (v[i] - m) * rs * gw[d] + gb[d];
    }
}

// ---------------- final-LN stats only (mean, rstd per row) ----------------
__global__ void ln_stats_kernel(const float* __restrict__ X) {
    int warp = threadIdx.x >> 5, lane = threadIdx.x & 31;
    int row = blockIdx.x * 8 + warp;
    const float* x = X + (size_t)row * 256;
    float v[8];
#pragma unroll
    for (int i = 0; i < 8; i++) v[i] = x[lane + i * 32];
    float s = 0.f;
#pragma unroll
    for (int i = 0; i < 8; i++) s += v[i];
#pragma unroll
    for (int o = 16; o > 0; o >>= 1) s += __shfl_xor_sync(0xffffffffu, s, o);
    float m = s * (1.0f / 256.0f);
    float q = 0.f;
#pragma unroll
    for (int i = 0; i < 8; i++) { float d = v[i] - m; q += d * d; }
#pragma unroll
    for (int o = 16; o > 0; o >>= 1) q += __shfl_xor_sync(0xffffffffu, q, o);
    float rs = rsqrtf(q * (1.0f / 256.0f) + 1e-5f);
    if (lane == 0) g_stats[row] = make_float2(m, rs);
}

// ---------------- tf32 GEMM with cp.async 2-stage pipeline ----------------
// MODE 1: gate (K=512: k<256 from A=f, k>=256 from A2=r; N=256; out = g*f+(1-g)*r)
// MODE 2: oproj(K=256, N=256; out += val + bias  (residual))
#define GEMM_SMEM (2 * (128 * 36 + 64 * 36) * 4)

template <int MODE>
__global__ __launch_bounds__(256)
void gemm_kernel(const float* __restrict__ A, const float* __restrict__ A2,
                 const float* __restrict__ W, const float* __restrict__ bias,
                 float* __restrict__ out) {
    extern __shared__ float smg[];
    float* sAb = smg;                  // 2 x 128 x 36
    float* sBb = smg + 2 * 128 * 36;   // 2 x 64 x 36
    const int KT  = (MODE == 1) ? 512 : 256;
    const int WLD = (MODE == 1) ? 512 : 256;
    const int NIT = KT / 32;
    int tid = threadIdx.x, lane = tid & 31, warp = tid >> 5;
    int wm = warp >> 1, wn = warp & 1;
    int rowBase = blockIdx.y * 128;
    int colBase = blockIdx.x * 64;
    int g = lane >> 2, q = lane & 3;

    float acc[2][4][4];
#pragma unroll
    for (int a = 0; a < 2; a++)
#pragma unroll
        for (int b = 0; b < 4; b++)
#pragma unroll
            for (int c = 0; c < 4; c++) acc[a][b][c] = 0.f;

    auto stage = [&](int bsel, int k0) {
        const float* Asrc = (MODE == 1 && k0 >= 256) ? A2 : A;
        int kA = (MODE == 1) ? (k0 & 255) : k0;
        float* dA = sAb + bsel * 128 * 36;
#pragma unroll
        for (int i = 0; i < 4; i++) {
            int flat = tid + i * 256;
            int r = flat >> 3, c4 = flat & 7;
            cp16(&dA[r * 36 + c4 * 4], &Asrc[(size_t)(rowBase + r) * 256 + kA + c4 * 4]);
        }
        float* dB = sBb + bsel * 64 * 36;
#pragma unroll
        for (int i = 0; i < 2; i++) {
            int flat = tid + i * 256;
            int r = flat >> 3, c4 = flat & 7;
            cp16(&dB[r * 36 + c4 * 4], &W[(size_t)(colBase + r) * WLD + k0 + c4 * 4]);
        }
    };

    stage(0, 0); cp_commit();
    for (int it = 0; it < NIT; it++) {
        if (it + 1 < NIT) { stage((it + 1) & 1, (it + 1) * 32); cp_commit(); cp_wait<1>(); }
        else cp_wait<0>();
        __syncthreads();
        const float* sA = sAb + (it & 1) * 128 * 36;
        const float* sB = sBb + (it & 1) * 64 * 36;
#pragma unroll
        for (int kk = 0; kk < 4; kk++) {
            int ko = kk * 8;
            unsigned a[2][4];
#pragma unroll
            for (int mt = 0; mt < 2; mt++) {
                int rb2 = wm * 32 + mt * 16;
                a[mt][0] = __float_as_uint(sA[(rb2 + g) * 36 + ko + q]);
                a[mt][1] = __float_as_uint(sA[(rb2 + g + 8) * 36 + ko + q]);
                a[mt][2] = __float_as_uint(sA[(rb2 + g) * 36 + ko + q + 4]);
                a[mt][3] = __float_as_uint(sA[(rb2 + g + 8) * 36 + ko + q + 4]);
            }
#pragma unroll
            for (int nt = 0; nt < 4; nt++) {
                int nb = wn * 32 + nt * 8;
                unsigned b0 = __float_as_uint(sB[(nb + g) * 36 + ko + q]);
                unsigned b1 = __float_as_uint(sB[(nb + g) * 36 + ko + q + 4]);
                mma_tf32(acc[0][nt], a[0], b0, b1);
                mma_tf32(acc[1][nt], a[1], b0, b1);
            }
        }
        __syncthreads();
    }
#pragma unroll
    for (int mt = 0; mt < 2; mt++)
#pragma unroll
        for (int nt = 0; nt < 4; nt++)
#pragma unroll
            for (int i = 0; i < 4; i++) {
                int row = rowBase + wm * 32 + mt * 16 + g + ((i & 2) ? 8 : 0);
                int coln = colBase + wn * 32 + nt * 8 + 2 * q + (i & 1);
                float val = acc[mt][nt][i] + bias[coln];
                if (MODE == 1) {
                    float gg = sigf(val);
                    float fv = A [(size_t)row * 256 + coln];
                    float rv = A2[(size_t)row * 256 + coln];
                    out[(size_t)row * 256 + coln] = gg * fv + (1.0f - gg) * rv;
                } else {
                    out[(size_t)row * 256 + coln] += val;
                }
            }
}

// ---------------- merged xi GEMM (F + R in one launch): K=256, N=768 each ----------------
__global__ __launch_bounds__(256)
void xi_kernel(const float* __restrict__ A,
               const float* __restrict__ Wf, const float* __restrict__ Wr,
               const float* __restrict__ bf, const float* __restrict__ br,
               float* __restrict__ outF, float* __restrict__ outR) {
    extern __shared__ float smg[];
    float* sAb = smg;
    float* sBb = smg + 2 * 128 * 36;
    bool rev = blockIdx.x >= 12;
    const float* W    = rev ? Wr : Wf;
    const float* bias = rev ? br : bf;
    float* out        = rev ? outR : outF;
    int colBase = (rev ? (int)blockIdx.x - 12 : (int)blockIdx.x) * 64;
    int rowBase = blockIdx.y * 128;
    int tid = threadIdx.x, lane = tid & 31, warp = tid >> 5;
    int wm = warp >> 1, wn = warp & 1;
    int g = lane >> 2, q = lane & 3;

    float acc[2][4][4];
#pragma unroll
    for (int a = 0; a < 2; a++)
#pragma unroll
        for (int b = 0; b < 4; b++)
#pragma unroll
            for (int c = 0; c < 4; c++) acc[a][b][c] = 0.f;

    auto stage = [&](int bsel, int k0) {
        float* dA = sAb + bsel * 128 * 36;
#pragma unroll
        for (int i = 0; i < 4; i++) {
            int flat = tid + i * 256;
            int r = flat >> 3, c4 = flat & 7;
            cp16(&dA[r * 36 + c4 * 4], &A[(size_t)(rowBase + r) * 256 + k0 + c4 * 4]);
        }
        float* dB = sBb + bsel * 64 * 36;
#pragma unroll
        for (int i = 0; i < 2; i++) {
            int flat = tid + i * 256;
            int r = flat >> 3, c4 = flat & 7;
            cp16(&dB[r * 36 + c4 * 4], &W[(size_t)(colBase + r) * 256 + k0 + c4 * 4]);
        }
    };

    stage(0, 0); cp_commit();
    for (int it = 0; it < 8; it++) {
        if (it + 1 < 8) { stage((it + 1) & 1, (it + 1) * 32); cp_commit(); cp_wait<1>(); }
        else cp_wait<0>();
        __syncthreads();
        const float* sA = sAb + (it & 1) * 128 * 36;
        const float* sB = sBb + (it & 1) * 64 * 36;
#pragma unroll
        for (int kk = 0; kk < 4; kk++) {
            int ko = kk * 8;
            unsigned a[2][4];
#pragma unroll
            for (int mt = 0; mt < 2; mt++) {
                int rb2 = wm * 32 + mt * 16;
                a[mt][0] = __float_as_uint(sA[(rb2 + g) * 36 + ko + q]);
                a[mt][1] = __float_as_uint(sA[(rb2 + g + 8) * 36 + ko + q]);
                a[mt][2] = __float_as_uint(sA[(rb2 + g) * 36 + ko + q + 4]);
                a[mt][3] = __float_as_uint(sA[(rb2 + g + 8) * 36 + ko + q + 4]);
            }
#pragma unroll
            for (int nt = 0; nt < 4; nt++) {
                int nb = wn * 32 + nt * 8;
                unsigned b0 = __float_as_uint(sB[(nb + g) * 36 + ko + q]);
                unsigned b1 = __float_as_uint(sB[(nb + g) * 36 + ko + q + 4]);
                mma_tf32(acc[0][nt], a[0], b0, b1);
                mma_tf32(acc[1][nt], a[1], b0, b1);
            }
        }
        __syncthreads();
    }
#pragma unroll
    for (int mt = 0; mt < 2; mt++)
#pragma unroll
        for (int nt = 0; nt < 4; nt++)
#pragma unroll
            for (int i = 0; i < 4; i++) {
                int row = rowBase + wm * 32 + mt * 16 + g + ((i & 2) ? 8 : 0);
                int coln = colBase + wn * 32 + nt * 8 + 2 * q + (i & 1);
                out[(size_t)row * 768 + coln] = acc[mt][nt][i] + bias[coln];
            }
}

// ---------------- persistent bidirectional GRU scan ----------------
// 128 CTAs: dir(2) x batch-slice(4, 16 rows) x unit-slice(16, 16 hidden units).
// R13: ONE __syncthreads per step. Warp-local h staging (syncwarp), per-warp
// release (lane0 red.release after syncwarp; 64 releases/step), all-thread
// acquire poll. The group-wide poll itself serializes sRed/buf reuse, so the
// pre-release and post-poll CTA barriers are provably redundant.
#define RNN_SMEM ((48*260 + 16*260 + 4*16*48 + 48) * 4)

__global__ __launch_bounds__(128)
void rnn_kernel(const float* __restrict__ whhF, const float* __restrict__ whhR,
                const float* __restrict__ bhhF, const float* __restrict__ bhhR) {
    extern __shared__ float sm[];
    float* sW   = sm;                 // 48 x 260 (tf32)  [init only]
    float* sH   = sW + 48 * 260;      // 16 x 260 (tf32 h tile; warp-local quarters)
    float* sRed = sH + 16 * 260;      // 4 warps x 16 x 48 partials
    float* sBhh = sRed + 4 * 16 * 48; // 48

    int cta = blockIdx.x;
    int dir = cta >> 6, rem = cta & 63, bs = rem >> 4, u = rem & 15;
    int group = dir * 4 + bs;
    const float* W    = dir ? whhR : whhF;
    const float* bhh  = dir ? bhhR : bhhF;
    const float* xi   = dir ? g_xir : g_xif;
    float*       outp = dir ? g_r   : g_f;
    float*    buf = g_hbuf + (size_t)group * 8192;   // 2 x 16 x 256
    unsigned* cnt = &g_cnt[group * 64];

    int tid = threadIdx.x, lane = tid & 31, warp = tid >> 5;
    int g = lane >> 2, q = lane & 3;
    int kbase = warp * 64;

    // load weight slice -> tf32 in SMEM
    for (int idx = tid; idx < 48 * 256; idx += 128) {
        int rI = idx >> 8, k = idx & 255;
        int grow = (rI >> 4) * 256 + u * 16 + (rI & 15);
        sW[rI * 260 + k] = f2tff(W[(size_t)grow * 256 + k]);
    }
    if (tid < 48) {
        int grow = (tid >> 4) * 256 + u * 16 + (tid & 15);
        sBhh[tid] = bhh[grow];
    }
    // zero my block of h buffer parity 0
    for (int idx = tid; idx < 256; idx += 128) {
        int lr = idx >> 4, c = idx & 15;
        buf[lr * 256 + u * 16 + c] = 0.f;
    }
    __syncthreads();

    // hoist Whh fragments into registers
    unsigned bfr[8][6][2];
#pragma unroll
    for (int ks = 0; ks < 8; ks++) {
        int k0 = kbase + ks * 8;
#pragma unroll
        for (int j = 0; j < 6; j++) {
            bfr[ks][j][0] = __float_as_uint(sW[(j * 8 + g) * 260 + k0 + q]);
            bfr[ks][j][1] = __float_as_uint(sW[(j * 8 + g) * 260 + k0 + q + 4]);
        }
    }

    // init release (zero-stores observed via the syncthreads above)
    if (tid == 0) red_rel(cnt, 1u);
    unsigned target = 16u;
    while (ld_acq(cnt) < target) {}    // all threads acquire

    // per-thread cell mapping (2 cells)
    int uc = tid & 15;
    int gu = u * 16 + uc;
    int lr0 = tid >> 4;        // 0..7
    int lr1 = lr0 + 8;         // 8..15

    float hpc0 = 0.f, hpc1 = 0.f;   // h_0 = 0, carried in registers

    // xi prefetch for t=0
    float xr0, xz0, xn0, xr1, xz1, xn1;
    {
        int tt = dir ? 1023 : 0;
        const float* x0 = xi + ((size_t)(bs * 16 + lr0) * 1024 + tt) * 768;
        const float* x1 = xi + ((size_t)(bs * 16 + lr1) * 1024 + tt) * 768;
        xr0 = x0[gu]; xz0 = x0[256 + gu]; xn0 = x0[512 + gu];
        xr1 = x1[gu]; xz1 = x1[256 + gu]; xn1 = x1[512 + gu];
    }

    for (int t = 0; t < 1024; t++) {
        int par = t & 1;
        int ttime = dir ? (1023 - t) : t;
        size_t row0 = (size_t)(bs * 16 + lr0) * 1024 + ttime;
        size_t row1 = (size_t)(bs * 16 + lr1) * 1024 + ttime;

        // warp-local stage: this warp's k-quarter [kbase, kbase+64), all 16 rows
#pragma unroll
        for (int it = 0; it < 8; it++) {
            int idx = lane + it * 32;          // 0..255
            int lr = idx >> 4, c4 = idx & 15;
            float4 v = *(const float4*)&buf[par * 4096 + lr * 256 + kbase + c4 * 4];
            float4 w;
            w.x = f2tff(v.x); w.y = f2tff(v.y); w.z = f2tff(v.z); w.w = f2tff(v.w);
            *(float4*)&sH[lr * 260 + kbase + c4 * 4] = w;
        }
        __syncwarp();

        // MMA over this warp's k-quarter; b operands register-resident
        float c[6][4];
#pragma unroll
        for (int j = 0; j < 6; j++)
#pragma unroll
            for (int i = 0; i < 4; i++) c[j][i] = 0.f;
#pragma unroll
        for (int ks = 0; ks < 8; ks++) {
            int k0 = kbase + ks * 8;
            unsigned a[4];
            a[0] = __float_as_uint(sH[g * 260 + k0 + q]);
            a[1] = __float_as_uint(sH[(g + 8) * 260 + k0 + q]);
            a[2] = __float_as_uint(sH[g * 260 + k0 + q + 4]);
            a[3] = __float_as_uint(sH[(g + 8) * 260 + k0 + q + 4]);
#pragma unroll
            for (int j = 0; j < 6; j++)
                mma_tf32(c[j], a, bfr[ks][j][0], bfr[ks][j][1]);
        }
        // dump partials
        {
            float* rw = sRed + warp * 768;
#pragma unroll
            for (int j = 0; j < 6; j++) {
                *(float2*)&rw[g * 48 + j * 8 + 2 * q]       = make_float2(c[j][0], c[j][1]);
                *(float2*)&rw[(g + 8) * 48 + j * 8 + 2 * q] = make_float2(c[j][2], c[j][3]);
            }
        }
        __syncthreads();   // the single per-step CTA barrier (dump -> reduce)

        // reduce + GRU pointwise (sRed + xi regs + register hp only)
        float hv0, hv1;
        {
            int o = lr0 * 48;
            float gr = sRed[o + uc]      + sRed[768 + o + uc]      + sRed[1536 + o + uc]      + sRed[2304 + o + uc];
            float gz = sRed[o + 16 + uc] + sRed[768 + o + 16 + uc] + sRed[1536 + o + 16 + uc] + sRed[2304 + o + 16 + uc];
            float gn = sRed[o + 32 + uc] + sRed[768 + o + 32 + uc] + sRed[1536 + o + 32 + uc] + sRed[2304 + o + 32 + uc];
            float rr = sigf(xr0 + gr + sBhh[uc]);
            float zz = sigf(xz0 + gz + sBhh[16 + uc]);
            float nn = tanhf(xn0 + rr * (gn + sBhh[32 + uc]));
            hv0 = (1.0f - zz) * nn + zz * hpc0;
        }
        {
            int o = lr1 * 48;
            float gr = sRed[o + uc]      + sRed[768 + o + uc]      + sRed[1536 + o + uc]      + sRed[2304 + o + uc];
            float gz = sRed[o + 16 + uc] + sRed[768 + o + 16 + uc] + sRed[1536 + o + 16 + uc] + sRed[2304 + o + 16 + uc];
            float gn = sRed[o + 32 + uc] + sRed[768 + o + 32 + uc] + sRed[1536 + o + 32 + uc] + sRed[2304 + o + 32 + uc];
            float rr = sigf(xr1 + gr + sBhh[uc]);
            float zz = sigf(xz1 + gz + sBhh[16 + uc]);
            float nn = tanhf(xn1 + rr * (gn + sBhh[32 + uc]));
            hv1 = (1.0f - zz) * nn + zz * hpc1;
        }
        hpc0 = hv0; hpc1 = hv1;
        // publish next-h slice; per-warp release (cumulative over warp stores)
        buf[(1 - par) * 4096 + lr0 * 256 + gu] = hv0;
        buf[(1 - par) * 4096 + lr1 * 256 + gu] = hv1;
        __syncwarp();
        if (lane == 0) red_rel(cnt, 1u);

        // off-critical-path: streaming outputs + xi prefetch for t+1
        outp[row0 * 256 + gu] = hv0;
        outp[row1 * 256 + gu] = hv1;
        if (t + 1 < 1024) {
            int tt = dir ? (1023 - (t + 1)) : (t + 1);
            const float* x0 = xi + ((size_t)(bs * 16 + lr0) * 1024 + tt) * 768;
            const float* x1 = xi + ((size_t)(bs * 16 + lr1) * 1024 + tt) * 768;
            xr0 = x0[gu]; xz0 = x0[256 + gu]; xn0 = x0[512 + gu];
            xr1 = x1[gu]; xz1 = x1[256 + gu]; xn1 = x1[512 + gu];
        }

        target += 64u;                      // 16 CTAs x 4 warps per step
        while (ld_acq(cnt) < target) {}     // all threads acquire-poll
    }
}

// ---------------- pooling: partial sum of (h-m)*rs over S chunks, both encodes ----------------
__global__ void pool_kernel() {
    int b = blockIdx.x, cch = blockIdx.y, d = threadIdx.x;
    size_t r0 = (size_t)b * 1024 + cch * 256;
    size_t r1 = (size_t)(32 + b) * 1024 + cch * 256;
    const float* h0 = g_h + r0 * 256 + d;
    const float* h1 = g_h + r1 * 256 + d;
    float s = 0.f;
#pragma unroll 4
    for (int si = 0; si < 256; si++) {
        float2 a = g_stats[r0 + si];
        float2 c = g_stats[r1 + si];
        s += (h0[(size_t)si * 256] - a.x) * a.y + (h1[(size_t)si * 256] - c.x) * c.y;
    }
    g_pool[((size_t)cch * 32 + b) * 256 + d] = s;
}

// ---------------- head: apply final-LN gain/bias to pooled, proj O=64, LN, GELU ----------------
__global__ void head_kernel(const float* __restrict__ fng, const float* __restrict__ fnb,
                            const float* __restrict__ pw, const float* __restrict__ pb,
                            const float* __restrict__ pg, const float* __restrict__ pbt,
                            float* __restrict__ out) {
    __shared__ float pooled[256];
    __shared__ float sp[64];
    int b = blockIdx.x, o = threadIdx.x;   // 64 threads
    for (int k = o; k < 256; k += 64) {
        float s = 0.f;
#pragma unroll
        for (int cch = 0; cch < 4; cch++) s += g_pool[((size_t)cch * 32 + b) * 256 + k];
        pooled[k] = s * (0.5f / 1024.0f) * fng[k] + fnb[k];
    }
    __syncthreads();
    float acc = pb[o];
    for (int k = 0; k < 256; k++) acc += pooled[k] * pw[o * 256 + k];
    sp[o] = acc;
    __syncthreads();
    float m = 0.f;
    for (int k = 0; k < 64; k++) m += sp[k];
    m *= (1.0f / 64.0f);
    float v = 0.f;
    for (int k = 0; k < 64; k++) { float d = sp[k] - m; v += d * d; }
    v *= (1.0f / 64.0f);
    float y = (acc - m) * rsqrtf(v + 1e-5f) * pg[o] + pbt[o];
    out[b * 64 + o] = y * 0.5f * (1.0f + erff(y * 0.70710678118654752f));
}

// ---------------- launch ----------------
extern "C" void kernel_launch(void* const* d_in, const int* in_sizes, int n_in,
                              void* d_out, int out_size) {
    const int*   tok  = (const int*)  d_in[0];
    const float* emb  = (const float*)d_in[1];
    const float* pos  = (const float*)d_in[2];
    const float* lng  = (const float*)d_in[3];
    const float* lnb  = (const float*)d_in[4];
    const float* wihF = (const float*)d_in[5];
    const float* whhF = (const float*)d_in[6];
    const float* bihF = (const float*)d_in[7];
    const float* bhhF = (const float*)d_in[8];
    const float* wihR = (const float*)d_in[9];
    const float* whhR = (const float*)d_in[10];
    const float* bihR = (const float*)d_in[11];
    const float* bhhR = (const float*)d_in[12];
    const float* wg   = (const float*)d_in[13];
    const float* bg   = (const float*)d_in[14];
    const float* wo   = (const float*)d_in[15];
    const float* bo   = (const float*)d_in[16];
    const float* fng  = (const float*)d_in[17];
    const float* fnb  = (const float*)d_in[18];
    const float* pw   = (const float*)d_in[19];
    const float* pb   = (const float*)d_in[20];
    const float* plg  = (const float*)d_in[21];
    const float* plb  = (const float*)d_in[22];

    float* hf; float* hr; float* xif; float* xir; float* hnp; float* hp; void* cntp;
    cudaGetSymbolAddress((void**)&hf,  g_f);
    cudaGetSymbolAddress((void**)&hr,  g_r);
    cudaGetSymbolAddress((void**)&xif, g_xif);
    cudaGetSymbolAddress((void**)&xir, g_xir);
    cudaGetSymbolAddress((void**)&hnp, g_hn);
    cudaGetSymbolAddress((void**)&hp,  g_h);
    cudaGetSymbolAddress(&cntp, g_cnt);

    cudaFuncSetAttribute(rnn_kernel, cudaFuncAttributeMaxDynamicSharedMemorySize, RNN_SMEM);
    cudaFuncSetAttribute(xi_kernel, cudaFuncAttributeMaxDynamicSharedMemorySize, GEMM_SMEM);
    cudaFuncSetAttribute(gemm_kernel<1>, cudaFuncAttributeMaxDynamicSharedMemorySize, GEMM_SMEM);
    cudaFuncSetAttribute(gemm_kernel<2>, cudaFuncAttributeMaxDynamicSharedMemorySize, GEMM_SMEM);

    embed_kernel<<<65536, 256>>>(tok, emb, pos);

    for (int i = 0; i < 4; i++) {
        const float* wihFi = wihF + (size_t)i * 768 * 256;
        const float* whhFi = whhF + (size_t)i * 768 * 256;
        const float* bihFi = bihF + (size_t)i * 768;
        const float* bhhFi = bhhF + (size_t)i * 768;
        const float* wihRi = wihR + (size_t)i * 768 * 256;
        const float* whhRi = whhR + (size_t)i * 768 * 256;
        const float* bihRi = bihR + (size_t)i * 768;
        const float* bhhRi = bhhR + (size_t)i * 768;
        const float* wgi   = wg + (size_t)i * 256 * 512;
        const float* bgi   = bg + (size_t)i * 256;
        const float* woi   = wo + (size_t)i * 256 * 256;
        const float* boi   = bo + (size_t)i * 256;

        ln_kernel<<<8192, 256>>>(hp, lng + i * 256, lnb + i * 256, hnp);
        xi_kernel<<<dim3(24, 512), 256, GEMM_SMEM>>>(hnp, wihFi, wihRi, bihFi, bihRi, xif, xir);
        cudaMemsetAsync(cntp, 0, 8 * 64 * sizeof(unsigned));
        rnn_kernel<<<128, 128, RNN_SMEM>>>(whhFi, whhRi, bhhFi, bhhRi);
        gemm_kernel<1><<<dim3(4, 512), 256, GEMM_SMEM>>>(hf, hr, wgi, bgi, hnp);      // hn <- gated c
        gemm_kernel<2><<<dim3(4, 512), 256, GEMM_SMEM>>>(hnp, nullptr, woi, boi, hp); // h += c@wo^T+bo
    }

    ln_stats_kernel<<<8192, 256>>>(hp);
    pool_kernel<<<dim3(32, 4), 256>>>();
    head_kernel<<<32, 64>>>(fng, fnb, pw, pb, plg, plb, (float*)d_out);
}